// round 5
// baseline (speedup 1.0000x reference)
#include <cuda_runtime.h>
#include <cuda_bf16.h>
#include <cstdint>

#define S_LEN 2048
#define HID   512
#define IN_D  128
#define OUT_D 64
#define ALPHA 0.2f
#define CLU   8          // CTAs per cluster = hidden-column splits
#define NGRP  16         // batch groups (clusters)

typedef unsigned long long ull;

// ---- dynamic smem layout (float offsets) ----
#define H_ROW   520
#define H_BUF   (4 * H_ROW)              // 2080
#define H_OFF   0                        // h[2][4][520]
#define RED_OFF (2 * H_BUF)              // 4160
#define RED_ROW 260
#define WHO_OFF (RED_OFF + 16 * RED_ROW) // 8320
#define WHO_ROW 520
#define SMEM_FLOATS (WHO_OFF + 8 * WHO_ROW) // 12480
#define SMEM_BYTES  (SMEM_FLOATS * 4)       // 49920

// h state exchange through L2 (double-buffered)
__device__ float g_hbuf[2][64 * HID];

// ---------------- packed f32x2 helpers ----------------
__device__ __forceinline__ ull fma2(ull a, ull b, ull c) {
    ull d;
    asm("fma.rn.f32x2 %0, %1, %2, %3;" : "=l"(d) : "l"(a), "l"(b), "l"(c));
    return d;
}
__device__ __forceinline__ ull pack2(float a, float b) {
    ull r;
    asm("mov.b64 %0, {%1, %2};" : "=l"(r) : "r"(__float_as_uint(a)), "r"(__float_as_uint(b)));
    return r;
}
__device__ __forceinline__ float lo2(ull v) { return __uint_as_float((unsigned)(v & 0xffffffffull)); }
__device__ __forceinline__ float hi2(ull v) { return __uint_as_float((unsigned)(v >> 32)); }
__device__ __forceinline__ float my_tanh(float v) {
    float e = __expf(2.0f * v);          // inf -> exactly +1 branch-free
    return 1.0f - 2.0f / (e + 1.0f);
}

// split cluster barrier: arrive has release, wait has acquire semantics
__device__ __forceinline__ void clu_arrive() {
    asm volatile("barrier.cluster.arrive.aligned;" ::: "memory");
}
__device__ __forceinline__ void clu_wait() {
    asm volatile("barrier.cluster.wait.aligned;" ::: "memory");
}

// warp-tiled readout: out[b0..b0+1][srow][o0..o0+1] from full h buffer in smem
__device__ __forceinline__ void do_readout(const float* hbuf, const float* who,
                                           int warp, int lane, int g, int cs,
                                           int srow, float* out) {
    const int b0 = (warp >> 2) * 2;
    const int o0 = (warp & 3) * 2;
    const ulonglong2* h0p = (const ulonglong2*)(hbuf + b0 * H_ROW + lane * 16);
    const ulonglong2* h1p = (const ulonglong2*)(hbuf + (b0 + 1) * H_ROW + lane * 16);
    const ulonglong2* w0p = (const ulonglong2*)(who + o0 * WHO_ROW + lane * 16);
    const ulonglong2* w1p = (const ulonglong2*)(who + (o0 + 1) * WHO_ROW + lane * 16);
    ull a00 = 0, a01 = 0, a10 = 0, a11 = 0;
#pragma unroll
    for (int c = 0; c < 4; c++) {
        ulonglong2 h0 = h0p[c], h1 = h1p[c], w0 = w0p[c], w1 = w1p[c];
        a00 = fma2(h0.x, w0.x, a00); a00 = fma2(h0.y, w0.y, a00);
        a01 = fma2(h0.x, w1.x, a01); a01 = fma2(h0.y, w1.y, a01);
        a10 = fma2(h1.x, w0.x, a10); a10 = fma2(h1.y, w0.y, a10);
        a11 = fma2(h1.x, w1.x, a11); a11 = fma2(h1.y, w1.y, a11);
    }
    float f00 = lo2(a00) + hi2(a00), f01 = lo2(a01) + hi2(a01);
    float f10 = lo2(a10) + hi2(a10), f11 = lo2(a11) + hi2(a11);
#pragma unroll
    for (int off = 16; off; off >>= 1) {
        f00 += __shfl_xor_sync(~0u, f00, off);
        f01 += __shfl_xor_sync(~0u, f01, off);
        f10 += __shfl_xor_sync(~0u, f10, off);
        f11 += __shfl_xor_sync(~0u, f11, off);
    }
    if (lane == 0) {
        size_t base = ((size_t)(g * 4 + b0) * S_LEN + srow) * OUT_D + cs * 8 + o0;
        size_t rstride = (size_t)S_LEN * OUT_D;
        out[base] = f00;           out[base + 1] = f01;
        out[base + rstride] = f10; out[base + rstride + 1] = f11;
    }
}

__global__ void __launch_bounds__(256, 1) __cluster_dims__(CLU, 1, 1)
rnn_clb_kernel(const float* __restrict__ x,     // [64][2048][128]
               const float* __restrict__ Wih,   // [128][512]
               const float* __restrict__ Wrec,  // [512][512]
               const float* __restrict__ Who,   // [512][64]
               float* __restrict__ out)         // [64][2048][64]
{
    extern __shared__ float smem[];
    float* h_s   = smem + H_OFF;     // [2][4][520]
    float* red   = smem + RED_OFF;   // [16][260]
    float* who_s = smem + WHO_OFF;   // [8][520]

    const int t    = threadIdx.x;
    const int warp = t >> 5, lane = t & 31;
    const int g    = blockIdx.x >> 3;      // batch group (cluster id)
    const int cs   = blockIdx.x & 7;       // cluster rank = column split

    // compute-thread mapping
    const int nj = t & 15;                 // 16 n-groups of 4 cols
    const int ks = t >> 4;                 // 16 k-splits of 32 k
    const int n0 = cs * 64 + nj * 4;
    const int k0 = ks * 32;
    const int i0 = ks * 8;
    const int b_loc = t >> 6, nl = t & 63; // finalize mapping

    // ---- W_rec slice -> registers (k-pair packed) ----
    ull wr[64];
#pragma unroll
    for (int kp = 0; kp < 16; kp++) {
        float4 we = *(const float4*)&Wrec[(k0 + 2 * kp)     * HID + n0];
        float4 wo = *(const float4*)&Wrec[(k0 + 2 * kp + 1) * HID + n0];
        wr[kp * 4 + 0] = pack2(we.x, wo.x);
        wr[kp * 4 + 1] = pack2(we.y, wo.y);
        wr[kp * 4 + 2] = pack2(we.z, wo.z);
        wr[kp * 4 + 3] = pack2(we.w, wo.w);
    }
    ull wi[16];
#pragma unroll
    for (int ip = 0; ip < 4; ip++) {
        float4 we = *(const float4*)&Wih[(i0 + 2 * ip)     * HID + n0];
        float4 wo = *(const float4*)&Wih[(i0 + 2 * ip + 1) * HID + n0];
        wi[ip * 4 + 0] = pack2(we.x, wo.x);
        wi[ip * 4 + 1] = pack2(we.y, wo.y);
        wi[ip * 4 + 2] = pack2(we.z, wo.z);
        wi[ip * 4 + 3] = pack2(we.w, wo.w);
    }
    // Who o-slice transposed [o][k]
    for (int idx = t; idx < 8 * 512; idx += 256) {
        int ol = idx >> 9, k = idx & 511;
        who_s[ol * WHO_ROW + k] = Who[k * OUT_D + cs * 8 + ol];
    }
    // h0 = 0 in buffer 0
    for (int idx = t; idx < H_BUF; idx += 256) h_s[idx] = 0.0f;

    // acc = x@Wih partial for step 0 (h-independent)
    ull acc[16];
#pragma unroll
    for (int q = 0; q < 16; q++) acc[q] = 0ull;
#pragma unroll
    for (int c = 0; c < 2; c++) {
        int ii = i0 + c * 4;
#pragma unroll
        for (int b = 0; b < 4; b++) {
            float4 xa = *(const float4*)&x[((size_t)(g * 4 + b) * S_LEN + 0) * IN_D + ii];
            ull xe = pack2(xa.x, xa.y), xo = pack2(xa.z, xa.w);
#pragma unroll
            for (int j = 0; j < 4; j++) {
                acc[b * 4 + j] = fma2(xe, wi[(c * 2) * 4 + j],     acc[b * 4 + j]);
                acc[b * 4 + j] = fma2(xo, wi[(c * 2 + 1) * 4 + j], acc[b * 4 + j]);
            }
        }
    }

#pragma unroll 1
    for (int s = 0; s < S_LEN; s++) {
        const int ph = s & 1, pn = ph ^ 1;
        float* hb = h_s + ph * H_BUF;

        if (s) {
            clu_wait();                       // all peers published h_s (acquire)
            // stage full h_s (8KB) from L2 into smem
            const float* g_h = g_hbuf[ph];
            int off = t * 8;
            float4 a  = *(const float4*)&g_h[(size_t)g * 4 * HID + off];
            float4 b4 = *(const float4*)&g_h[(size_t)g * 4 * HID + off + 4];
            int bb2 = off >> 9, kk2 = off & 511;
            *(float4*)&hb[bb2 * H_ROW + kk2]     = a;
            *(float4*)&hb[bb2 * H_ROW + kk2 + 4] = b4;
        }
        __syncthreads();                      // S2: staging (and prologue) visible

        // ---- h@Wrec accumulate (acc already holds x@Wih for this step) ----
#pragma unroll
        for (int c = 0; c < 8; c++) {
            int kk = k0 + c * 4;
#pragma unroll
            for (int b = 0; b < 4; b++) {
                ulonglong2 h2 = *(const ulonglong2*)&hb[b * H_ROW + kk];
#pragma unroll
                for (int j = 0; j < 4; j++) {
                    acc[b * 4 + j] = fma2(h2.x, wr[(c * 2) * 4 + j],     acc[b * 4 + j]);
                    acc[b * 4 + j] = fma2(h2.y, wr[(c * 2 + 1) * 4 + j], acc[b * 4 + j]);
                }
            }
        }
        // partials -> smem
#pragma unroll
        for (int b = 0; b < 4; b++) {
            float4 v;
            v.x = lo2(acc[b * 4 + 0]) + hi2(acc[b * 4 + 0]);
            v.y = lo2(acc[b * 4 + 1]) + hi2(acc[b * 4 + 1]);
            v.z = lo2(acc[b * 4 + 2]) + hi2(acc[b * 4 + 2]);
            v.w = lo2(acc[b * 4 + 3]) + hi2(acc[b * 4 + 3]);
            *(float4*)&red[ks * RED_ROW + b * 64 + nj * 4] = v;
        }
        __syncthreads();                      // S1

        // reduce 16 k-splits
        float pre = 0.0f;
#pragma unroll
        for (int r = 0; r < 16; r++) pre += red[r * RED_ROW + t];

        // activation + leaky update; publish own value to L2
        float hold = hb[b_loc * H_ROW + cs * 64 + nl];
        float hnew = (1.0f - ALPHA) * hold + ALPHA * my_tanh(pre);
        g_hbuf[pn][(size_t)(g * 4 + b_loc) * HID + cs * 64 + nl] = hnew;

        clu_arrive();                         // release: publish visible after peers' wait

        // ======== overlap window (h-independent work) ========
        // x@Wih partial for next step
#pragma unroll
        for (int q = 0; q < 16; q++) acc[q] = 0ull;
        if (s + 1 < S_LEN) {
#pragma unroll
            for (int c = 0; c < 2; c++) {
                int ii = i0 + c * 4;
#pragma unroll
                for (int b = 0; b < 4; b++) {
                    float4 xa = *(const float4*)&x[((size_t)(g * 4 + b) * S_LEN + (s + 1)) * IN_D + ii];
                    ull xe = pack2(xa.x, xa.y), xo = pack2(xa.z, xa.w);
#pragma unroll
                    for (int j = 0; j < 4; j++) {
                        acc[b * 4 + j] = fma2(xe, wi[(c * 2) * 4 + j],     acc[b * 4 + j]);
                        acc[b * 4 + j] = fma2(xo, wi[(c * 2 + 1) * 4 + j], acc[b * 4 + j]);
                    }
                }
            }
        }
        // readout for previous step (h_s -> out row s-1)
        if (s) do_readout(hb, who_s, warp, lane, g, cs, s - 1, out);
    }

    // epilogue: h_2048 -> out row 2047
    clu_wait();
    {
        const float* g_h = g_hbuf[0];
        int off = t * 8;
        float4 a  = *(const float4*)&g_h[(size_t)g * 4 * HID + off];
        float4 b4 = *(const float4*)&g_h[(size_t)g * 4 * HID + off + 4];
        int bb2 = off >> 9, kk2 = off & 511;
        *(float4*)&h_s[bb2 * H_ROW + kk2]     = a;
        *(float4*)&h_s[bb2 * H_ROW + kk2 + 4] = b4;
    }
    __syncthreads();
    do_readout(h_s, who_s, warp, lane, g, cs, S_LEN - 1, out);
}

extern "C" void kernel_launch(void* const* d_in, const int* in_sizes, int n_in,
                              void* d_out, int out_size) {
    const float* x    = (const float*)d_in[0];
    const float* Wih  = (const float*)d_in[1];
    const float* Wrec = (const float*)d_in[2];
    const float* Who  = (const float*)d_in[3];
    float* out = (float*)d_out;

    cudaFuncSetAttribute(rnn_clb_kernel,
                         cudaFuncAttributeMaxDynamicSharedMemorySize, SMEM_BYTES);
    rnn_clb_kernel<<<NGRP * CLU, 256, SMEM_BYTES>>>(x, Wih, Wrec, Who, out);
}

// round 6
// speedup vs baseline: 1.8867x; 1.8867x over previous
#include <cuda_runtime.h>
#include <cuda_bf16.h>
#include <cstdint>

#define S_LEN 2048
#define HID   512
#define IN_D  128
#define OUT_D 64
#define ALPHA 0.2f
#define NCS   8          // hidden-column splits (CTAs per batch group)
#define NGRP  16         // batch groups

typedef unsigned long long ull;

// ---- dynamic smem layout (float offsets) ----
#define H_ROW   520
#define H_BUF   (4 * H_ROW)              // 2080
#define H_OFF   0                        // h[2][4][520]
#define RED_OFF (2 * H_BUF)              // 4160
#define RED_ROW 260
#define WHO_OFF (RED_OFF + 16 * RED_ROW) // 8320
#define WHO_ROW 520
#define SMEM_FLOATS (WHO_OFF + 8 * WHO_ROW) // 12480
#define SMEM_BYTES  (SMEM_FLOATS * 4)       // 49920

// L2-exchanged state (no allocations rule -> device globals)
__device__ float    g_hbuf[2][64 * HID];
__device__ unsigned g_cnt[NGRP * 32];       // 128B-padded per group

// ---------------- packed f32x2 helpers ----------------
__device__ __forceinline__ ull fma2(ull a, ull b, ull c) {
    ull d;
    asm("fma.rn.f32x2 %0, %1, %2, %3;" : "=l"(d) : "l"(a), "l"(b), "l"(c));
    return d;
}
__device__ __forceinline__ ull pack2(float a, float b) {
    ull r;
    asm("mov.b64 %0, {%1, %2};" : "=l"(r) : "r"(__float_as_uint(a)), "r"(__float_as_uint(b)));
    return r;
}
__device__ __forceinline__ float lo2(ull v) { return __uint_as_float((unsigned)(v & 0xffffffffull)); }
__device__ __forceinline__ float hi2(ull v) { return __uint_as_float((unsigned)(v >> 32)); }
__device__ __forceinline__ float my_tanh(float v) {
    float e = __expf(2.0f * v);          // inf -> exactly +1, branch-free
    return 1.0f - 2.0f / (e + 1.0f);
}
// release add (no return) / acquire load, GPU scope
__device__ __forceinline__ void rel_add1(unsigned* p) {
    asm volatile("red.release.gpu.add.u32 [%0], 1;" :: "l"(p) : "memory");
}
__device__ __forceinline__ unsigned acq_ld(const unsigned* p) {
    unsigned v;
    asm volatile("ld.acquire.gpu.u32 %0, [%1];" : "=r"(v) : "l"(p) : "memory");
    return v;
}

__global__ void rnn_init_kernel() {
    if (threadIdx.x < NGRP) g_cnt[threadIdx.x * 32] = 0u;
}

// warp-tiled readout: out[b0..b0+1][srow][o0..o0+1] from h buffer in smem
__device__ __forceinline__ void do_readout(const float* hbuf, const float* who,
                                           int warp, int lane, int g, int cs,
                                           int srow, float* out) {
    const int b0 = (warp >> 2) * 2;
    const int o0 = (warp & 3) * 2;
    const ulonglong2* h0p = (const ulonglong2*)(hbuf + b0 * H_ROW + lane * 16);
    const ulonglong2* h1p = (const ulonglong2*)(hbuf + (b0 + 1) * H_ROW + lane * 16);
    const ulonglong2* w0p = (const ulonglong2*)(who + o0 * WHO_ROW + lane * 16);
    const ulonglong2* w1p = (const ulonglong2*)(who + (o0 + 1) * WHO_ROW + lane * 16);
    ull a00 = 0, a01 = 0, a10 = 0, a11 = 0;
#pragma unroll
    for (int c = 0; c < 4; c++) {
        ulonglong2 h0 = h0p[c], h1 = h1p[c], w0 = w0p[c], w1 = w1p[c];
        a00 = fma2(h0.x, w0.x, a00); a00 = fma2(h0.y, w0.y, a00);
        a01 = fma2(h0.x, w1.x, a01); a01 = fma2(h0.y, w1.y, a01);
        a10 = fma2(h1.x, w0.x, a10); a10 = fma2(h1.y, w0.y, a10);
        a11 = fma2(h1.x, w1.x, a11); a11 = fma2(h1.y, w1.y, a11);
    }
    float f00 = lo2(a00) + hi2(a00), f01 = lo2(a01) + hi2(a01);
    float f10 = lo2(a10) + hi2(a10), f11 = lo2(a11) + hi2(a11);
#pragma unroll
    for (int off = 16; off; off >>= 1) {
        f00 += __shfl_xor_sync(~0u, f00, off);
        f01 += __shfl_xor_sync(~0u, f01, off);
        f10 += __shfl_xor_sync(~0u, f10, off);
        f11 += __shfl_xor_sync(~0u, f11, off);
    }
    if (lane == 0) {
        size_t base = ((size_t)(g * 4 + b0) * S_LEN + srow) * OUT_D + cs * 8 + o0;
        size_t rstride = (size_t)S_LEN * OUT_D;
        out[base] = f00;           out[base + 1] = f01;
        out[base + rstride] = f10; out[base + rstride + 1] = f11;
    }
}

__global__ void __launch_bounds__(256, 1)
rnn_fast_kernel(const float* __restrict__ x,     // [64][2048][128]
                const float* __restrict__ Wih,   // [128][512]
                const float* __restrict__ Wrec,  // [512][512]
                const float* __restrict__ Who,   // [512][64]
                float* __restrict__ out)         // [64][2048][64]
{
    extern __shared__ float smem[];
    float* h_s   = smem + H_OFF;     // [2][4][520]
    float* red   = smem + RED_OFF;   // [16][260]
    float* who_s = smem + WHO_OFF;   // [8][520]

    const int t    = threadIdx.x;
    const int warp = t >> 5, lane = t & 31;
    const int g    = blockIdx.x >> 3;      // batch group
    const int cs   = blockIdx.x & 7;       // column split

    // compute-thread mapping
    const int nj = t & 15;                 // 16 n-groups of 4 cols
    const int ks = t >> 4;                 // 16 k-splits of 32 k
    const int n0 = cs * 64 + nj * 4;
    const int k0 = ks * 32;
    const int i0 = ks * 8;
    const int b_loc = t >> 6, nl = t & 63; // finalize mapping
    unsigned* cnt = &g_cnt[g * 32];

    // ---- W_rec slice -> registers (k-pair packed) ----
    ull wr[64];
#pragma unroll
    for (int kp = 0; kp < 16; kp++) {
        float4 we = *(const float4*)&Wrec[(k0 + 2 * kp)     * HID + n0];
        float4 wo = *(const float4*)&Wrec[(k0 + 2 * kp + 1) * HID + n0];
        wr[kp * 4 + 0] = pack2(we.x, wo.x);
        wr[kp * 4 + 1] = pack2(we.y, wo.y);
        wr[kp * 4 + 2] = pack2(we.z, wo.z);
        wr[kp * 4 + 3] = pack2(we.w, wo.w);
    }
    ull wi[16];
#pragma unroll
    for (int ip = 0; ip < 4; ip++) {
        float4 we = *(const float4*)&Wih[(i0 + 2 * ip)     * HID + n0];
        float4 wo = *(const float4*)&Wih[(i0 + 2 * ip + 1) * HID + n0];
        wi[ip * 4 + 0] = pack2(we.x, wo.x);
        wi[ip * 4 + 1] = pack2(we.y, wo.y);
        wi[ip * 4 + 2] = pack2(we.z, wo.z);
        wi[ip * 4 + 3] = pack2(we.w, wo.w);
    }
    // Who o-slice transposed [o][k]
    for (int idx = t; idx < 8 * 512; idx += 256) {
        int ol = idx >> 9, k = idx & 511;
        who_s[ol * WHO_ROW + k] = Who[k * OUT_D + cs * 8 + ol];
    }
    // h0 = 0 in buffer 0
    for (int idx = t; idx < H_BUF; idx += 256) h_s[idx] = 0.0f;

    // acc preloaded with x@Wih for step 0
    ull acc[16];
#pragma unroll
    for (int q = 0; q < 16; q++) acc[q] = 0ull;
#pragma unroll
    for (int c = 0; c < 2; c++) {
        int ii = i0 + c * 4;
#pragma unroll
        for (int b = 0; b < 4; b++) {
            float4 xa = *(const float4*)&x[((size_t)(g * 4 + b) * S_LEN + 0) * IN_D + ii];
            ull xe = pack2(xa.x, xa.y), xo = pack2(xa.z, xa.w);
#pragma unroll
            for (int j = 0; j < 4; j++) {
                acc[b * 4 + j] = fma2(xe, wi[(c * 2) * 4 + j],     acc[b * 4 + j]);
                acc[b * 4 + j] = fma2(xo, wi[(c * 2 + 1) * 4 + j], acc[b * 4 + j]);
            }
        }
    }
    __syncthreads();

#pragma unroll 1
    for (int s = 0; s < S_LEN; s++) {
        const int ph = s & 1, pn = ph ^ 1;
        float* hb = h_s + ph * H_BUF;

        // ---- h@Wrec accumulate (acc already holds x@Wih for this step) ----
#pragma unroll
        for (int c = 0; c < 8; c++) {
            int kk = k0 + c * 4;
#pragma unroll
            for (int b = 0; b < 4; b++) {
                ulonglong2 h2 = *(const ulonglong2*)&hb[b * H_ROW + kk];
#pragma unroll
                for (int j = 0; j < 4; j++) {
                    acc[b * 4 + j] = fma2(h2.x, wr[(c * 2) * 4 + j],     acc[b * 4 + j]);
                    acc[b * 4 + j] = fma2(h2.y, wr[(c * 2 + 1) * 4 + j], acc[b * 4 + j]);
                }
            }
        }
        // partials -> smem
#pragma unroll
        for (int b = 0; b < 4; b++) {
            float4 v;
            v.x = lo2(acc[b * 4 + 0]) + hi2(acc[b * 4 + 0]);
            v.y = lo2(acc[b * 4 + 1]) + hi2(acc[b * 4 + 1]);
            v.z = lo2(acc[b * 4 + 2]) + hi2(acc[b * 4 + 2]);
            v.w = lo2(acc[b * 4 + 3]) + hi2(acc[b * 4 + 3]);
            *(float4*)&red[ks * RED_ROW + b * 64 + nj * 4] = v;
        }
        __syncthreads();                      // S1

        // reduce 16 k-splits
        float pre = 0.0f;
#pragma unroll
        for (int r = 0; r < 16; r++) pre += red[r * RED_ROW + t];

        // activation + leaky update; publish own value (weak store)
        float hold = hb[b_loc * H_ROW + cs * 64 + nl];
        float hnew = (1.0f - ALPHA) * hold + ALPHA * my_tanh(pre);
        g_hbuf[pn][(size_t)(g * 4 + b_loc) * HID + cs * 64 + nl] = hnew;
        __syncthreads();                      // S2: block's stores ordered before release

        if (t == 0) rel_add1(cnt);            // release: publishes block's h stores

        // ======== overlap window (h-independent) ========
        // x@Wih partial for next step
#pragma unroll
        for (int q = 0; q < 16; q++) acc[q] = 0ull;
        if (s + 1 < S_LEN) {
#pragma unroll
            for (int c = 0; c < 2; c++) {
                int ii = i0 + c * 4;
#pragma unroll
                for (int b = 0; b < 4; b++) {
                    float4 xa = *(const float4*)&x[((size_t)(g * 4 + b) * S_LEN + (s + 1)) * IN_D + ii];
                    ull xe = pack2(xa.x, xa.y), xo = pack2(xa.z, xa.w);
#pragma unroll
                    for (int j = 0; j < 4; j++) {
                        acc[b * 4 + j] = fma2(xe, wi[(c * 2) * 4 + j],     acc[b * 4 + j]);
                        acc[b * 4 + j] = fma2(xo, wi[(c * 2 + 1) * 4 + j], acc[b * 4 + j]);
                    }
                }
            }
        }
        // readout of previous step (reads current hb, untouched this phase)
        if (s) do_readout(hb, who_s, warp, lane, g, cs, s - 1, out);

        // ---- all-thread acquire poll (one L2 req per warp, broadcast line) ----
        {
            unsigned target = 8u * (unsigned)(s + 1);
            while (acq_ld(cnt) < target) { }
        }
        // stage h_{s+1} into next buffer via L1-bypass loads
        {
            const float* g_h = g_hbuf[pn];
            int off = t * 8;
            float4 a  = __ldcg((const float4*)&g_h[(size_t)g * 4 * HID + off]);
            float4 b4 = __ldcg((const float4*)&g_h[(size_t)g * 4 * HID + off + 4]);
            int bb2 = off >> 9, kk2 = off & 511;
            float* hn = h_s + pn * H_BUF;
            *(float4*)&hn[bb2 * H_ROW + kk2]     = a;
            *(float4*)&hn[bb2 * H_ROW + kk2 + 4] = b4;
        }
        __syncthreads();                      // S3: staged h visible to all
    }

    // epilogue: h_2048 is in buffer 0 -> out row 2047
    do_readout(h_s, who_s, warp, lane, g, cs, S_LEN - 1, out);
}

extern "C" void kernel_launch(void* const* d_in, const int* in_sizes, int n_in,
                              void* d_out, int out_size) {
    const float* x    = (const float*)d_in[0];
    const float* Wih  = (const float*)d_in[1];
    const float* Wrec = (const float*)d_in[2];
    const float* Who  = (const float*)d_in[3];
    float* out = (float*)d_out;

    rnn_init_kernel<<<1, 32>>>();
    cudaFuncSetAttribute(rnn_fast_kernel,
                         cudaFuncAttributeMaxDynamicSharedMemorySize, SMEM_BYTES);
    rnn_fast_kernel<<<NGRP * NCS, 256, SMEM_BYTES>>>(x, Wih, Wrec, Who, out);
}

// round 8
// speedup vs baseline: 2.6069x; 1.3818x over previous
#include <cuda_runtime.h>
#include <cuda_bf16.h>
#include <cstdint>

#define S_LEN 2048
#define HID   512
#define IN_D  128
#define OUT_D 64
#define ALPHA 0.2f
#define NCS   8          // column-split CTAs per batch group
#define NGRP  16         // batch groups
#define NTHR  512

typedef unsigned long long ull;

// ---- dynamic smem layout (float offsets) ----
#define H_ROW   520
#define H_BUF   (4 * H_ROW)                  // 2080
#define H_OFF   0                            // h[2][4][520]
#define X_OFF   (2 * H_BUF)                  // 4160 : x[2][512]
#define RED_ROW 264
#define RED_OFF (X_OFF + 2 * 512)            // 5184 : red[16][264]
#define WHO_ROW 520
#define WHO_OFF (RED_OFF + 16 * RED_ROW)     // 9408 : who[8][520]
#define WIH_OFF (WHO_OFF + 8 * WHO_ROW)      // 13568 : packed Wih, 4096 ull = 8192 floats
#define SMEM_FLOATS (WIH_OFF + 8192)         // 21760
#define SMEM_BYTES  (SMEM_FLOATS * 4)        // 87040

// L2-exchanged state
__device__ float    g_hbuf[2][64 * HID];
__device__ unsigned g_cnt[NGRP * 32];

// ---------------- packed f32x2 helpers ----------------
__device__ __forceinline__ ull fma2(ull a, ull b, ull c) {
    ull d;
    asm("fma.rn.f32x2 %0, %1, %2, %3;" : "=l"(d) : "l"(a), "l"(b), "l"(c));
    return d;
}
__device__ __forceinline__ ull pack2(float a, float b) {
    ull r;
    asm("mov.b64 %0, {%1, %2};" : "=l"(r) : "r"(__float_as_uint(a)), "r"(__float_as_uint(b)));
    return r;
}
__device__ __forceinline__ float lo2(ull v) { return __uint_as_float((unsigned)(v & 0xffffffffull)); }
__device__ __forceinline__ float hi2(ull v) { return __uint_as_float((unsigned)(v >> 32)); }
__device__ __forceinline__ float my_tanh(float v) {
    float e = __expf(2.0f * v);               // inf -> exactly +1, branch-free
    return 1.0f - __fdividef(2.0f, e + 1.0f);
}
__device__ __forceinline__ void rel_add1(unsigned* p) {
    asm volatile("red.release.gpu.add.u32 [%0], 1;" :: "l"(p) : "memory");
}
__device__ __forceinline__ unsigned acq_ld(const unsigned* p) {
    unsigned v;
    asm volatile("ld.acquire.gpu.u32 %0, [%1];" : "=r"(v) : "l"(p) : "memory");
    return v;
}

__global__ void rnn_init_kernel() {
    if (threadIdx.x < NGRP) g_cnt[threadIdx.x * 32] = 0u;
}

// conflict-free warp-tiled readout: warp w -> (b = w&3, o0 = (w>>2)*2)
__device__ __forceinline__ void do_readout(const float* hbuf, const float* who,
                                           int warp, int lane, int g, int cs,
                                           int srow, float* __restrict__ out) {
    const int b  = warp & 3;
    const int o0 = (warp >> 2) * 2;
    ull a0 = 0, a1 = 0;
#pragma unroll
    for (int c = 0; c < 4; c++) {
        int kk = c * 128 + lane * 4;                   // 16B lane stride: conflict-free
        ulonglong2 h2 = *(const ulonglong2*)&hbuf[b * H_ROW + kk];
        ulonglong2 w0 = *(const ulonglong2*)&who[o0 * WHO_ROW + kk];
        ulonglong2 w1 = *(const ulonglong2*)&who[(o0 + 1) * WHO_ROW + kk];
        a0 = fma2(h2.x, w0.x, a0); a0 = fma2(h2.y, w0.y, a0);
        a1 = fma2(h2.x, w1.x, a1); a1 = fma2(h2.y, w1.y, a1);
    }
    float f0 = lo2(a0) + hi2(a0);
    float f1 = lo2(a1) + hi2(a1);
#pragma unroll
    for (int off = 16; off; off >>= 1) {
        f0 += __shfl_xor_sync(~0u, f0, off);
        f1 += __shfl_xor_sync(~0u, f1, off);
    }
    if (lane == 0) {
        size_t base = ((size_t)(g * 4 + b) * S_LEN + srow) * OUT_D + cs * 8 + o0;
        out[base]     = f0;
        out[base + 1] = f1;
    }
}

__global__ void __launch_bounds__(NTHR, 1)
rnn_w512_kernel(const float* __restrict__ x,     // [64][2048][128]
                const float* __restrict__ Wih,   // [128][512]
                const float* __restrict__ Wrec,  // [512][512]
                const float* __restrict__ Who,   // [512][64]
                float* __restrict__ out)         // [64][2048][64]
{
    extern __shared__ float smem[];
    float* h_s   = smem + H_OFF;     // [2][4][520]
    float* x_s   = smem + X_OFF;     // [2][512]
    float* red   = smem + RED_OFF;   // [16][264]
    float* who_s = smem + WHO_OFF;   // [8][520]
    ull*   wih_s = (ull*)(smem + WIH_OFF);  // [16 ks][4 ip][64 (nj*2+j)] = 4096 ull

    const int t    = threadIdx.x;
    const int warp = t >> 5, lane = t & 31;
    const int g    = blockIdx.x >> 3;      // batch group
    const int cs   = blockIdx.x & 7;       // column split

    // compute mapping: 32 n-groups of 2 cols, 16 k-splits of 32 k
    const int nj = t & 31;
    const int ks = t >> 5;                 // == warp (whole warp same k-split)
    const int n0 = cs * 64 + nj * 2;
    const int k0 = ks * 32;
    const int i0 = ks * 8;
    unsigned* cnt = &g_cnt[g * 32];

    // ---- W_rec slice -> registers, k-pair packed: wr[16 kp][2 j] ----
    ull wr[32];
#pragma unroll
    for (int kp = 0; kp < 16; kp++) {
        float2 we = *(const float2*)&Wrec[(k0 + 2 * kp)     * HID + n0];
        float2 wo = *(const float2*)&Wrec[(k0 + 2 * kp + 1) * HID + n0];
        wr[kp * 2 + 0] = pack2(we.x, wo.x);
        wr[kp * 2 + 1] = pack2(we.y, wo.y);
    }
    // ---- Wih slice -> packed smem: [ks][ip][nj*2 + j] ----
#pragma unroll
    for (int ip = 0; ip < 4; ip++) {
        float2 we = *(const float2*)&Wih[(i0 + 2 * ip)     * HID + n0];
        float2 wo = *(const float2*)&Wih[(i0 + 2 * ip + 1) * HID + n0];
        wih_s[(ks * 4 + ip) * 64 + nj * 2 + 0] = pack2(we.x, wo.x);
        wih_s[(ks * 4 + ip) * 64 + nj * 2 + 1] = pack2(we.y, wo.y);
    }
    // Who o-slice transposed [o][k]
    for (int idx = t; idx < 8 * 512; idx += NTHR) {
        int ol = idx >> 9, k = idx & 511;
        who_s[ol * WHO_ROW + k] = Who[k * OUT_D + cs * 8 + ol];
    }
    // h0 = 0 in buffer 0; stage x[s=0]
    for (int idx = t; idx < H_BUF; idx += NTHR) h_s[idx] = 0.0f;
    {
        int row = t >> 7, col = t & 127;
        x_s[row * 128 + col] = x[((size_t)(g * 4 + row) * S_LEN) * IN_D + col];
    }
    __syncthreads();

#pragma unroll 1
    for (int s = 0; s < S_LEN; s++) {
        const int ph = s & 1, pn = ph ^ 1;
        const float* hb = h_s + ph * H_BUF;
        const float* xb = x_s + ph * 512;

        // prefetch next x early (consumed next step; STS after S2)
        float xn = 0.0f;
        const int xrow = t >> 7, xcol = t & 127;
        if (s + 1 < S_LEN)
            xn = x[((size_t)(g * 4 + xrow) * S_LEN + (s + 1)) * IN_D + xcol];

        // ---- pre-activation partials: h@Wrec + x@Wih ----
        ull acc[8];
#pragma unroll
        for (int q = 0; q < 8; q++) acc[q] = 0ull;

#pragma unroll
        for (int c = 0; c < 8; c++) {
            int kk = k0 + c * 4;
#pragma unroll
            for (int b = 0; b < 4; b++) {
                ulonglong2 h2 = *(const ulonglong2*)&hb[b * H_ROW + kk];  // warp-broadcast
                acc[b * 2 + 0] = fma2(h2.x, wr[(c * 2) * 2 + 0],     acc[b * 2 + 0]);
                acc[b * 2 + 1] = fma2(h2.x, wr[(c * 2) * 2 + 1],     acc[b * 2 + 1]);
                acc[b * 2 + 0] = fma2(h2.y, wr[(c * 2 + 1) * 2 + 0], acc[b * 2 + 0]);
                acc[b * 2 + 1] = fma2(h2.y, wr[(c * 2 + 1) * 2 + 1], acc[b * 2 + 1]);
            }
        }
#pragma unroll
        for (int ip = 0; ip < 4; ip++) {
            ulonglong2 wv = *(const ulonglong2*)&wih_s[(ks * 4 + ip) * 64 + nj * 2];
#pragma unroll
            for (int b = 0; b < 4; b++) {
                float2 xv = *(const float2*)&xb[b * 128 + i0 + 2 * ip]; // warp-broadcast
                ull xp = pack2(xv.x, xv.y);
                acc[b * 2 + 0] = fma2(xp, wv.x, acc[b * 2 + 0]);
                acc[b * 2 + 1] = fma2(xp, wv.y, acc[b * 2 + 1]);
            }
        }
        // partials -> red[ks][b*64 + nj*2 + j]
#pragma unroll
        for (int b = 0; b < 4; b++) {
            float2 v;
            v.x = lo2(acc[b * 2 + 0]) + hi2(acc[b * 2 + 0]);
            v.y = lo2(acc[b * 2 + 1]) + hi2(acc[b * 2 + 1]);
            *(float2*)&red[ks * RED_ROW + b * 64 + nj * 2] = v;
        }
        __syncthreads();                          // S1

        // reduce + activation + publish (t < 256: one output each)
        if (t < 256) {
            const int ob = t >> 6, oc = t & 63;
            float pre = 0.0f;
#pragma unroll
            for (int r = 0; r < 16; r++) pre += red[r * RED_ROW + ob * 64 + oc];
            float hold = hb[ob * H_ROW + cs * 64 + oc];
            float hnew = (1.0f - ALPHA) * hold + ALPHA * my_tanh(pre);
            g_hbuf[pn][(size_t)(g * 4 + ob) * HID + cs * 64 + oc] = hnew;
        }
        __syncthreads();                          // S2: publishes done
        if (t == 0) rel_add1(cnt);                // release

        // ---- overlap window: x staging + readout of previous step ----
        *(float*)&x_s[pn * 512 + xrow * 128 + xcol] = xn;
        if (s) do_readout(hb, who_s, warp, lane, g, cs, s - 1, out);

        // ---- acquire poll + stage h_{s+1} ----
        {
            unsigned target = 8u * (unsigned)(s + 1);
            while (acq_ld(cnt) < target) { }
        }
        {
            const float* g_h = g_hbuf[pn];
            float4 v = __ldcg((const float4*)&g_h[(size_t)g * 4 * HID + t * 4]);
            float* hn = h_s + pn * H_BUF;
            *(float4*)&hn[(t >> 7) * H_ROW + ((t * 4) & 511)] = v;
        }
        __syncthreads();                          // S3
    }

    // epilogue: h_2048 is in buffer 0 -> out row 2047
    do_readout(h_s, who_s, warp, lane, g, cs, S_LEN - 1, out);
}

extern "C" void kernel_launch(void* const* d_in, const int* in_sizes, int n_in,
                              void* d_out, int out_size) {
    const float* x    = (const float*)d_in[0];
    const float* Wih  = (const float*)d_in[1];
    const float* Wrec = (const float*)d_in[2];
    const float* Who  = (const float*)d_in[3];
    float* out = (float*)d_out;

    rnn_init_kernel<<<1, 32>>>();
    cudaFuncSetAttribute(rnn_w512_kernel,
                         cudaFuncAttributeMaxDynamicSharedMemorySize, SMEM_BYTES);
    rnn_w512_kernel<<<NGRP * NCS, NTHR, SMEM_BYTES>>>(x, Wih, Wrec, Who, out);
}